// round 9
// baseline (speedup 1.0000x reference)
#include <cuda_runtime.h>
#include <cuda_bf16.h>
#include <math.h>
#include <stdint.h>

// Problem constants
#define NNODES   31
#define VV       50000
#define HH       128
#define LBL      104
#define BB       64
#define LL       128
#define BL       (BB*LL)        // 8192
#define G3       384            // 3*H
#define G6       768            // both directions

// ---------------- device scratch (no allocations allowed) ----------------
__device__ float d_P[VV * 128];          // projected vocab table
__device__ float d_enc[BL * 128];        // encodes
__device__ float d_gi[BL * G6];          // input gates, both dirs
__device__ float d_whht[2 * G3 * HH];    // Whh transposed, k-major
__device__ float d_pooled[BB * 2 * HH];  // max-pooled GRU outputs

// ==================== MMA GEMM (bf16 3-term split) ========================
__device__ __forceinline__ void mma16816(float c[4], const uint32_t a[4],
                                         const uint32_t b[2]) {
    asm volatile(
        "mma.sync.aligned.m16n8k16.row.col.f32.bf16.bf16.f32 "
        "{%0,%1,%2,%3}, {%4,%5,%6,%7}, {%8,%9}, {%0,%1,%2,%3};"
        : "+f"(c[0]), "+f"(c[1]), "+f"(c[2]), "+f"(c[3])
        : "r"(a[0]), "r"(a[1]), "r"(a[2]), "r"(a[3]),
          "r"(b[0]), "r"(b[1]));
}

// explicit bit-level split+pack: element with LOWER k in LOWER 16 bits.
__device__ __forceinline__ void split_pack(float a, float b,
                                           uint32_t& hi, uint32_t& lo) {
    __nv_bfloat16 ha = __float2bfloat16(a);
    __nv_bfloat16 hb = __float2bfloat16(b);
    float fa = __bfloat162float(ha);
    float fb = __bfloat162float(hb);
    __nv_bfloat16 la = __float2bfloat16(a - fa);
    __nv_bfloat16 lb = __float2bfloat16(b - fb);
    hi = (uint32_t)__bfloat16_as_ushort(ha) |
         ((uint32_t)__bfloat16_as_ushort(hb) << 16);
    lo = (uint32_t)__bfloat16_as_ushort(la) |
         ((uint32_t)__bfloat16_as_ushort(lb) << 16);
}

#define SSTRW 68                        // padded stride (words): bank = 4g+tg, conflict-free
#define TILE_BYTES (128 * SSTRW * 4)    // 34816 B
#define GEMM_SMEM_BYTES (512 + 3 * TILE_BYTES)   // 104960 B -> 2 CTAs/SM

// one K-sweep of 8x(m16n8k16) x 16 mma accumulating Ah/Al x Bh/Blo product
__device__ __forceinline__ void mma_pass(const uint32_t* __restrict__ At,
                                         const uint32_t* __restrict__ Bt,
                                         float acc[2][8][4],
                                         int wm, int wn, int g, int tg)
{
#pragma unroll
    for (int kk = 0; kk < 8; kk++) {
        const int ko = kk * 8;
        uint32_t afr[2][4];
#pragma unroll
        for (int mt = 0; mt < 2; mt++) {
            int mr = wm * 32 + mt * 16;
            afr[mt][0] = At[(mr + g)     * SSTRW + tg     + ko];
            afr[mt][1] = At[(mr + g + 8) * SSTRW + tg     + ko];
            afr[mt][2] = At[(mr + g)     * SSTRW + tg + 4 + ko];
            afr[mt][3] = At[(mr + g + 8) * SSTRW + tg + 4 + ko];
        }
#pragma unroll
        for (int j = 0; j < 8; j++) {
            int nb = wn * 64 + j * 8 + g;
            uint32_t bfr[2];
            bfr[0] = Bt[nb * SSTRW + tg     + ko];
            bfr[1] = Bt[nb * SSTRW + tg + 4 + ko];
            mma16816(acc[0][j], afr[0], bfr);
            mma16816(acc[1][j], afr[1], bfr);
        }
    }
}

__global__ void __launch_bounds__(256, 2)
gemm3_mma_kernel(const float* __restrict__ A, int M,
                 const float* __restrict__ Bf, const float* __restrict__ Bb,
                 const float* __restrict__ biasf, const float* __restrict__ biasb,
                 float* __restrict__ C, int N_total)
{
    extern __shared__ char smem[];
    float*    bias_s = (float*)smem;                       // 128 floats
    uint32_t* Ah = (uint32_t*)(smem + 512);
    uint32_t* Ax = (uint32_t*)(smem + 512 + TILE_BYTES);   // Al, later Blo
    uint32_t* Bh = (uint32_t*)(smem + 512 + 2 * TILE_BYTES);

    const int tid = threadIdx.x;
    const int wid = tid >> 5;
    const int lane = tid & 31;
    const int g  = lane >> 2;
    const int tg = lane & 3;
    const int wm = wid & 3;
    const int wn = wid >> 2;
    const int row0 = blockIdx.x * 128;
    const int col0 = blockIdx.y * 128;

    if (tid < 128) {
        float bv = 0.f;
        if (biasf) {
            int gg = col0 + tid;
            bv = (gg < G3) ? biasf[gg] : biasb[gg - G3];
        }
        bias_s[tid] = bv;
    }

    // ---- fill A hi/lo ----
#pragma unroll 4
    for (int i = 0; i < 16; i++) {
        int idx = i * 256 + tid;
        int r   = idx >> 5;
        int k0  = (idx & 31) * 4;
        int grow = row0 + r;
        float4 v = (grow < M)
            ? *(const float4*)&A[(size_t)grow * 128 + k0]
            : make_float4(0.f, 0.f, 0.f, 0.f);
        uint32_t h0, h1, l0, l1;
        split_pack(v.x, v.y, h0, l0);
        split_pack(v.z, v.w, h1, l1);
        int wo = r * SSTRW + (k0 >> 1);
        *(uint2*)&Ah[wo] = make_uint2(h0, h1);
        *(uint2*)&Ax[wo] = make_uint2(l0, l1);
    }

    // ---- fill B hi ----
#pragma unroll 4
    for (int i = 0; i < 16; i++) {
        int idx = i * 256 + tid;
        int r   = idx >> 5;
        int k0  = (idx & 31) * 4;
        int gg  = col0 + r;
        const float* src = (Bb && gg >= G3) ? (Bb + (size_t)(gg - G3) * 128)
                                            : (Bf + (size_t)gg * 128);
        float4 v = *(const float4*)&src[k0];
        uint32_t h0, h1, l0, l1;
        split_pack(v.x, v.y, h0, l0);
        split_pack(v.z, v.w, h1, l1);
        int wo = r * SSTRW + (k0 >> 1);
        *(uint2*)&Bh[wo] = make_uint2(h0, h1);
        (void)l0; (void)l1;
    }
    __syncthreads();

    float acc[2][8][4];
#pragma unroll
    for (int mt = 0; mt < 2; mt++)
#pragma unroll
        for (int j = 0; j < 8; j++)
#pragma unroll
            for (int q = 0; q < 4; q++) acc[mt][j][q] = 0.f;

    // passes with {Ah, Al, Bh} resident
    mma_pass(Ah, Bh, acc, wm, wn, g, tg);   // Ah * Bh
    mma_pass(Ax, Bh, acc, wm, wn, g, tg);   // Al * Bh
    __syncthreads();

    // overwrite Al slot with Blo (re-split B from L2)
#pragma unroll 4
    for (int i = 0; i < 16; i++) {
        int idx = i * 256 + tid;
        int r   = idx >> 5;
        int k0  = (idx & 31) * 4;
        int gg  = col0 + r;
        const float* src = (Bb && gg >= G3) ? (Bb + (size_t)(gg - G3) * 128)
                                            : (Bf + (size_t)gg * 128);
        float4 v = *(const float4*)&src[k0];
        uint32_t h0, h1, l0, l1;
        split_pack(v.x, v.y, h0, l0);
        split_pack(v.z, v.w, h1, l1);
        int wo = r * SSTRW + (k0 >> 1);
        *(uint2*)&Ax[wo] = make_uint2(l0, l1);
        (void)h0; (void)h1;
    }
    __syncthreads();

    mma_pass(Ah, Ax, acc, wm, wn, g, tg);   // Ah * Blo

    // ---- epilogue: direct STG with bias ----
#pragma unroll
    for (int mt = 0; mt < 2; mt++) {
        int r0 = row0 + wm * 32 + mt * 16 + g;
#pragma unroll
        for (int j = 0; j < 8; j++) {
            int cl = wn * 64 + j * 8 + tg * 2;
            int cg = col0 + cl;
            float b0 = bias_s[cl], b1 = bias_s[cl + 1];
            if (r0 < M)
                *(float2*)&C[(size_t)r0 * N_total + cg] =
                    make_float2(acc[mt][j][0] + b0, acc[mt][j][1] + b1);
            if (r0 + 8 < M)
                *(float2*)&C[(size_t)(r0 + 8) * N_total + cg] =
                    make_float2(acc[mt][j][2] + b0, acc[mt][j][3] + b1);
        }
    }
}

// ==================== rest of the model ===================================
__global__ void transpose_whh_kernel(const float* __restrict__ Wf,
                                     const float* __restrict__ Wb) {
    int idx = blockIdx.x * blockDim.x + threadIdx.x;
    const int per = G3 * HH;
    if (idx >= 2 * per) return;
    int d = idx / per;
    int r = idx - d * per;
    int j = r / HH;
    int k = r - j * HH;
    const float* W = d ? Wb : Wf;
    d_whht[d * per + k * G3 + j] = W[j * HH + k];
}

__global__ void __launch_bounds__(128) encode_kernel(
    const int* __restrict__ tokens,
    const float* __restrict__ Wcb)
{
    const int bl = blockIdx.x;
    const int c = threadIdx.x;
    __shared__ int tok[NNODES];
    if (c < NNODES) tok[c] = tokens[bl * NNODES + c];
    __syncthreads();

    float v[NNODES];
#pragma unroll
    for (int n = 0; n < NNODES; n++)
        v[n] = d_P[(size_t)tok[n] * 128 + c];
#pragma unroll
    for (int n = 14; n >= 0; n--)
        v[n] = v[n] + (v[2 * n + 1] + v[2 * n + 2]);

    const float bc = Wcb[c];
    float m = -INFINITY;
#pragma unroll
    for (int n = 0; n < NNODES; n++) {
        int cnt = (n == 0) ? 31 : (n < 3) ? 15 : (n < 7) ? 7 : (n < 15) ? 3 : 1;
        m = fmaxf(m, v[n] + (float)cnt * bc);
    }
    d_enc[bl * 128 + c] = m;
}

// ---------------- GRU: packed f32x2 FMA + fast activations ----------------
__device__ __forceinline__ unsigned long long ffma2u(
    unsigned long long a, unsigned long long b, unsigned long long c)
{
    unsigned long long d;
    asm("fma.rn.f32x2 %0, %1, %2, %3;" : "=l"(d) : "l"(a), "l"(b), "l"(c));
    return d;
}

// sigmoid via ex2.approx + rcp.approx (rel err ~1e-6)
__device__ __forceinline__ float sigmoid_fast(float x) {
    float e;
    asm("ex2.approx.f32 %0, %1;" : "=f"(e) : "f"(-1.4426950408889634f * x));
    float r;
    asm("rcp.approx.f32 %0, %1;" : "=f"(r) : "f"(1.f + e));
    return r;
}
// tanh(x) = 2*sigmoid(2x) - 1  (abs err ~1e-6, no cancellation blowup)
__device__ __forceinline__ float tanh_fast(float x) {
    return fmaf(2.f, sigmoid_fast(2.f * x), -1.f);
}

union F4U { float4 f; unsigned long long u[2]; };
union F2U { float2 f; unsigned long long u; };

__global__ void __launch_bounds__(384, 1) gru_kernel(
    const float* __restrict__ bhf, const float* __restrict__ bhb)
{
    const int dir = blockIdx.x >> 6;
    const int b   = blockIdx.x & 63;
    const int j   = threadIdx.x;

    __shared__ float h_s[HH];
    __shared__ float g_s[G3];

    const float* wt = d_whht + (size_t)dir * G3 * HH;
    unsigned long long w2[64];
#pragma unroll
    for (int k = 0; k < 64; k++) {
        F2U p;
        p.f.x = wt[(2 * k)     * G3 + j];
        p.f.y = wt[(2 * k + 1) * G3 + j];
        w2[k] = p.u;
    }

    const float bh = dir ? bhb[j] : bhf[j];
    if (j < HH) h_s[j] = 0.f;
    float pmax = -INFINITY;
    const float* gib = d_gi + (size_t)(b * LL) * G6 + dir * G3;

    F2U bh2;  bh2.f = make_float2(bh, 0.f);
    __syncthreads();

    for (int t = 0; t < LL; t++) {
        const int tt = dir ? (LL - 1 - t) : t;
        const float* girow = gib + (size_t)tt * G6;
        float gir = 0.f, giz = 0.f, gin = 0.f;
        if (j < HH) {   // prefetch input gates; latency hidden under the dot
            gir = girow[j];
            giz = girow[HH + j];
            gin = girow[2 * HH + j];
        }
        unsigned long long acc0 = bh2.u;
        F2U z2; z2.f = make_float2(0.f, 0.f);
        unsigned long long acc1 = z2.u;
#pragma unroll
        for (int k = 0; k < HH; k += 8) {
            F4U h0, h1;
            h0.f = *(const float4*)&h_s[k];
            h1.f = *(const float4*)&h_s[k + 4];
            acc0 = ffma2u(w2[k / 2 + 0], h0.u[0], acc0);
            acc1 = ffma2u(w2[k / 2 + 1], h0.u[1], acc1);
            acc0 = ffma2u(w2[k / 2 + 2], h1.u[0], acc0);
            acc1 = ffma2u(w2[k / 2 + 3], h1.u[1], acc1);
        }
        F2U a0, a1;  a0.u = acc0;  a1.u = acc1;
        g_s[j] = (a0.f.x + a0.f.y) + (a1.f.x + a1.f.y);
        __syncthreads();
        if (j < HH) {
            float r = sigmoid_fast(gir + g_s[j]);
            float z = sigmoid_fast(giz + g_s[HH + j]);
            float n = tanh_fast(gin + r * g_s[2 * HH + j]);
            float hn = (1.f - z) * n + z * h_s[j];
            h_s[j] = hn;
            pmax = fmaxf(pmax, hn);
        }
        __syncthreads();
    }
    if (j < HH) d_pooled[b * (2 * HH) + dir * HH + j] = pmax;
}

__global__ void __launch_bounds__(128) out_kernel(
    const float* __restrict__ Wout, const float* __restrict__ bout,
    float* __restrict__ out)
{
    const int b = blockIdx.x;
    const int tid = threadIdx.x;
    __shared__ float p_s[2 * HH];
    p_s[tid]      = d_pooled[b * 2 * HH + tid];
    p_s[tid + HH] = d_pooled[b * 2 * HH + HH + tid];
    __syncthreads();
    if (tid < LBL) {
        const float* wr = Wout + (size_t)tid * 2 * HH;
        float acc = bout[tid];
#pragma unroll 8
        for (int k = 0; k < 2 * HH; k++) acc = fmaf(wr[k], p_s[k], acc);
        out[b * LBL + tid] = acc;
    }
}

// ---------------- launch ---------------------------------------------------
extern "C" void kernel_launch(void* const* d_in, const int* in_sizes, int n_in,
                              void* d_out, int out_size) {
    const int*   tokens = (const int*)  d_in[0];
    const float* emb    = (const float*)d_in[1];
    const float* Wc_w   = (const float*)d_in[2];
    const float* Wc_b   = (const float*)d_in[3];
    const float* Wih_f  = (const float*)d_in[4];
    const float* Whh_f  = (const float*)d_in[5];
    const float* bih_f  = (const float*)d_in[6];
    const float* bhh_f  = (const float*)d_in[7];
    const float* Wih_b  = (const float*)d_in[8];
    const float* Whh_b  = (const float*)d_in[9];
    const float* bih_b  = (const float*)d_in[10];
    const float* bhh_b  = (const float*)d_in[11];
    const float* Wout   = (const float*)d_in[12];
    const float* bout   = (const float*)d_in[13];
    float* out = (float*)d_out;

    (void)in_sizes; (void)n_in; (void)out_size;

    cudaFuncSetAttribute(gemm3_mma_kernel,
                         cudaFuncAttributeMaxDynamicSharedMemorySize,
                         GEMM_SMEM_BYTES);

    float* dP = nullptr;  cudaGetSymbolAddress((void**)&dP, d_P);
    float* dG = nullptr;  cudaGetSymbolAddress((void**)&dG, d_gi);
    float* dE = nullptr;  cudaGetSymbolAddress((void**)&dE, d_enc);

    transpose_whh_kernel<<<(2 * G3 * HH + 255) / 256, 256>>>(Whh_f, Whh_b);

    // P = emb @ Wc_w^T  (tensor-core, 3-term bf16 split)
    gemm3_mma_kernel<<<dim3((VV + 127) / 128, 1), 256, GEMM_SMEM_BYTES>>>(
        emb, VV, Wc_w, nullptr, nullptr, nullptr, dP, 128);

    encode_kernel<<<BL, 128>>>(tokens, Wc_b);

    // gi = enc @ [Wih_f;Wih_b]^T + bias  (tensor-core)
    gemm3_mma_kernel<<<dim3(BL / 128, G6 / 128), 256, GEMM_SMEM_BYTES>>>(
        dE, BL, Wih_f, Wih_b, bih_f, bih_b, dG, G6);

    gru_kernel<<<128, 384>>>(bhh_f, bhh_b);
    out_kernel<<<BB, 128>>>(Wout, bout, out);
}

// round 10
// speedup vs baseline: 1.0689x; 1.0689x over previous
#include <cuda_runtime.h>
#include <cuda_bf16.h>
#include <math.h>
#include <stdint.h>

// Problem constants
#define NNODES   31
#define VV       50000
#define HH       128
#define LBL      104
#define BB       64
#define LL       128
#define BL       (BB*LL)        // 8192
#define G3       384            // 3*H
#define G6       768            // both directions

// ---------------- device scratch (no allocations allowed) ----------------
__device__ float d_P[VV * 128];          // projected vocab table
__device__ float d_enc[BL * 128];        // encodes
__device__ float d_gi[BL * G6];          // input gates, both dirs
__device__ float d_whht[2 * G3 * HH];    // Whh transposed, k-major
__device__ float d_pooled[BB * 2 * HH];  // max-pooled GRU outputs

// ==================== MMA GEMM (bf16 3-term split) ========================
__device__ __forceinline__ void mma16816(float c[4], const uint32_t a[4],
                                         const uint32_t b[2]) {
    asm volatile(
        "mma.sync.aligned.m16n8k16.row.col.f32.bf16.bf16.f32 "
        "{%0,%1,%2,%3}, {%4,%5,%6,%7}, {%8,%9}, {%0,%1,%2,%3};"
        : "+f"(c[0]), "+f"(c[1]), "+f"(c[2]), "+f"(c[3])
        : "r"(a[0]), "r"(a[1]), "r"(a[2]), "r"(a[3]),
          "r"(b[0]), "r"(b[1]));
}

// explicit bit-level split+pack: element with LOWER k in LOWER 16 bits.
__device__ __forceinline__ void split_pack(float a, float b,
                                           uint32_t& hi, uint32_t& lo) {
    __nv_bfloat16 ha = __float2bfloat16(a);
    __nv_bfloat16 hb = __float2bfloat16(b);
    float fa = __bfloat162float(ha);
    float fb = __bfloat162float(hb);
    __nv_bfloat16 la = __float2bfloat16(a - fa);
    __nv_bfloat16 lb = __float2bfloat16(b - fb);
    hi = (uint32_t)__bfloat16_as_ushort(ha) |
         ((uint32_t)__bfloat16_as_ushort(hb) << 16);
    lo = (uint32_t)__bfloat16_as_ushort(la) |
         ((uint32_t)__bfloat16_as_ushort(lb) << 16);
}

// Tile: 128(M) x 64(N), K=128. 8 warps as 4(m) x 2(n), warp tile 32x32.
// acc = 32 regs/thread -> fits 2 CTAs/SM with zero spills.
#define SSTRW 68                          // padded row stride in b32 words
#define TILE_A_BYTES (128 * SSTRW * 4)    // 34816
#define TILE_B_BYTES (64 * SSTRW * 4)     // 17408
#define GEMM_SMEM_BYTES (512 + 2 * TILE_A_BYTES + 2 * TILE_B_BYTES)  // 104960

__device__ __forceinline__ void mma_pass(const uint32_t* __restrict__ At,
                                         const uint32_t* __restrict__ Bt,
                                         float acc[2][4][4],
                                         int wm, int wn, int g, int tg)
{
#pragma unroll
    for (int kk = 0; kk < 8; kk++) {
        const int ko = kk * 8;
        uint32_t afr[2][4];
#pragma unroll
        for (int mt = 0; mt < 2; mt++) {
            int mr = wm * 32 + mt * 16;
            afr[mt][0] = At[(mr + g)     * SSTRW + tg     + ko];
            afr[mt][1] = At[(mr + g + 8) * SSTRW + tg     + ko];
            afr[mt][2] = At[(mr + g)     * SSTRW + tg + 4 + ko];
            afr[mt][3] = At[(mr + g + 8) * SSTRW + tg + 4 + ko];
        }
#pragma unroll
        for (int j = 0; j < 4; j++) {
            int nb = wn * 32 + j * 8 + g;
            uint32_t bfr[2];
            bfr[0] = Bt[nb * SSTRW + tg     + ko];
            bfr[1] = Bt[nb * SSTRW + tg + 4 + ko];
            mma16816(acc[0][j], afr[0], bfr);
            mma16816(acc[1][j], afr[1], bfr);
        }
    }
}

__global__ void __launch_bounds__(256, 2)
gemm3_mma_kernel(const float* __restrict__ A, int M,
                 const float* __restrict__ Bf, const float* __restrict__ Bb,
                 const float* __restrict__ biasf, const float* __restrict__ biasb,
                 float* __restrict__ C, int N_total)
{
    extern __shared__ char smem[];
    float*    bias_s = (float*)smem;                            // 64 floats
    uint32_t* Ah  = (uint32_t*)(smem + 512);
    uint32_t* Al  = (uint32_t*)(smem + 512 + TILE_A_BYTES);
    uint32_t* Bh  = (uint32_t*)(smem + 512 + 2 * TILE_A_BYTES);
    uint32_t* Blo = (uint32_t*)(smem + 512 + 2 * TILE_A_BYTES + TILE_B_BYTES);

    const int tid = threadIdx.x;
    const int wid = tid >> 5;
    const int lane = tid & 31;
    const int g  = lane >> 2;
    const int tg = lane & 3;
    const int wm = wid & 3;     // m block (32 rows)
    const int wn = wid >> 2;    // n block (32 cols)
    const int row0 = blockIdx.x * 128;
    const int col0 = blockIdx.y * 64;

    if (tid < 64) {
        float bv = 0.f;
        if (biasf) {
            int gg = col0 + tid;
            bv = (gg < G3) ? biasf[gg] : biasb[gg - G3];
        }
        bias_s[tid] = bv;
    }

    // ---- fill A hi/lo: 128 rows x 32 float4 = 4096 ----
#pragma unroll 4
    for (int i = 0; i < 16; i++) {
        int idx = i * 256 + tid;
        int r   = idx >> 5;
        int k0  = (idx & 31) * 4;
        int grow = row0 + r;
        float4 v = (grow < M)
            ? *(const float4*)&A[(size_t)grow * 128 + k0]
            : make_float4(0.f, 0.f, 0.f, 0.f);
        uint32_t h0, h1, l0, l1;
        split_pack(v.x, v.y, h0, l0);
        split_pack(v.z, v.w, h1, l1);
        int wo = r * SSTRW + (k0 >> 1);
        *(uint2*)&Ah[wo] = make_uint2(h0, h1);
        *(uint2*)&Al[wo] = make_uint2(l0, l1);
    }

    // ---- fill B hi/lo: 64 rows x 32 float4 = 2048 ----
#pragma unroll 4
    for (int i = 0; i < 8; i++) {
        int idx = i * 256 + tid;
        int r   = idx >> 5;
        int k0  = (idx & 31) * 4;
        int gg  = col0 + r;
        const float* src = (Bb && gg >= G3) ? (Bb + (size_t)(gg - G3) * 128)
                                            : (Bf + (size_t)gg * 128);
        float4 v = *(const float4*)&src[k0];
        uint32_t h0, h1, l0, l1;
        split_pack(v.x, v.y, h0, l0);
        split_pack(v.z, v.w, h1, l1);
        int wo = r * SSTRW + (k0 >> 1);
        *(uint2*)&Bh[wo]  = make_uint2(h0, h1);
        *(uint2*)&Blo[wo] = make_uint2(l0, l1);
    }
    __syncthreads();

    float acc[2][4][4];
#pragma unroll
    for (int mt = 0; mt < 2; mt++)
#pragma unroll
        for (int j = 0; j < 4; j++)
#pragma unroll
            for (int q = 0; q < 4; q++) acc[mt][j][q] = 0.f;

    mma_pass(Ah, Bh,  acc, wm, wn, g, tg);   // Ah * Bh
    mma_pass(Al, Bh,  acc, wm, wn, g, tg);   // Al * Bh
    mma_pass(Ah, Blo, acc, wm, wn, g, tg);   // Ah * Blo

    // ---- epilogue: direct STG with bias ----
#pragma unroll
    for (int mt = 0; mt < 2; mt++) {
        int r0 = row0 + wm * 32 + mt * 16 + g;
#pragma unroll
        for (int j = 0; j < 4; j++) {
            int cl = wn * 32 + j * 8 + tg * 2;   // local col
            int cg = col0 + cl;
            float b0 = bias_s[cl], b1 = bias_s[cl + 1];
            if (r0 < M)
                *(float2*)&C[(size_t)r0 * N_total + cg] =
                    make_float2(acc[mt][j][0] + b0, acc[mt][j][1] + b1);
            if (r0 + 8 < M)
                *(float2*)&C[(size_t)(r0 + 8) * N_total + cg] =
                    make_float2(acc[mt][j][2] + b0, acc[mt][j][3] + b1);
        }
    }
}

// ==================== rest of the model ===================================
__global__ void transpose_whh_kernel(const float* __restrict__ Wf,
                                     const float* __restrict__ Wb) {
    int idx = blockIdx.x * blockDim.x + threadIdx.x;
    const int per = G3 * HH;
    if (idx >= 2 * per) return;
    int d = idx / per;
    int r = idx - d * per;
    int j = r / HH;
    int k = r - j * HH;
    const float* W = d ? Wb : Wf;
    d_whht[d * per + k * G3 + j] = W[j * HH + k];
}

__global__ void __launch_bounds__(128) encode_kernel(
    const int* __restrict__ tokens,
    const float* __restrict__ Wcb)
{
    const int bl = blockIdx.x;
    const int c = threadIdx.x;
    __shared__ int tok[NNODES];
    if (c < NNODES) tok[c] = tokens[bl * NNODES + c];
    __syncthreads();

    float v[NNODES];
#pragma unroll
    for (int n = 0; n < NNODES; n++)
        v[n] = d_P[(size_t)tok[n] * 128 + c];
#pragma unroll
    for (int n = 14; n >= 0; n--)
        v[n] = v[n] + (v[2 * n + 1] + v[2 * n + 2]);

    const float bc = Wcb[c];
    float m = -INFINITY;
#pragma unroll
    for (int n = 0; n < NNODES; n++) {
        int cnt = (n == 0) ? 31 : (n < 3) ? 15 : (n < 7) ? 7 : (n < 15) ? 3 : 1;
        m = fmaxf(m, v[n] + (float)cnt * bc);
    }
    d_enc[bl * 128 + c] = m;
}

// ---------------- GRU: packed f32x2 FMA + fast activations ----------------
__device__ __forceinline__ unsigned long long ffma2u(
    unsigned long long a, unsigned long long b, unsigned long long c)
{
    unsigned long long d;
    asm("fma.rn.f32x2 %0, %1, %2, %3;" : "=l"(d) : "l"(a), "l"(b), "l"(c));
    return d;
}

// sigmoid via ex2.approx + rcp.approx (rel err ~1e-6)
__device__ __forceinline__ float sigmoid_fast(float x) {
    float e;
    asm("ex2.approx.f32 %0, %1;" : "=f"(e) : "f"(-1.4426950408889634f * x));
    float r;
    asm("rcp.approx.f32 %0, %1;" : "=f"(r) : "f"(1.f + e));
    return r;
}
// tanh(x) = 2*sigmoid(2x) - 1  (abs err ~1e-6)
__device__ __forceinline__ float tanh_fast(float x) {
    return fmaf(2.f, sigmoid_fast(2.f * x), -1.f);
}

union F4U { float4 f; unsigned long long u[2]; };
union F2U { float2 f; unsigned long long u; };

__global__ void __launch_bounds__(384, 1) gru_kernel(
    const float* __restrict__ bhf, const float* __restrict__ bhb)
{
    const int dir = blockIdx.x >> 6;
    const int b   = blockIdx.x & 63;
    const int j   = threadIdx.x;

    __shared__ float h_s[HH];
    __shared__ float g_s[G3];

    const float* wt = d_whht + (size_t)dir * G3 * HH;
    unsigned long long w2[64];
#pragma unroll
    for (int k = 0; k < 64; k++) {
        F2U p;
        p.f.x = wt[(2 * k)     * G3 + j];
        p.f.y = wt[(2 * k + 1) * G3 + j];
        w2[k] = p.u;
    }

    const float bh = dir ? bhb[j] : bhf[j];
    if (j < HH) h_s[j] = 0.f;
    float pmax = -INFINITY;
    const float* gib = d_gi + (size_t)(b * LL) * G6 + dir * G3;

    F2U bh2;  bh2.f = make_float2(bh, 0.f);
    __syncthreads();

    for (int t = 0; t < LL; t++) {
        const int tt = dir ? (LL - 1 - t) : t;
        const float* girow = gib + (size_t)tt * G6;
        float gir = 0.f, giz = 0.f, gin = 0.f;
        if (j < HH) {   // prefetch input gates; latency hidden under the dot
            gir = girow[j];
            giz = girow[HH + j];
            gin = girow[2 * HH + j];
        }
        unsigned long long acc0 = bh2.u;
        F2U z2; z2.f = make_float2(0.f, 0.f);
        unsigned long long acc1 = z2.u;
#pragma unroll
        for (int k = 0; k < HH; k += 8) {
            F4U h0, h1;
            h0.f = *(const float4*)&h_s[k];
            h1.f = *(const float4*)&h_s[k + 4];
            acc0 = ffma2u(w2[k / 2 + 0], h0.u[0], acc0);
            acc1 = ffma2u(w2[k / 2 + 1], h0.u[1], acc1);
            acc0 = ffma2u(w2[k / 2 + 2], h1.u[0], acc0);
            acc1 = ffma2u(w2[k / 2 + 3], h1.u[1], acc1);
        }
        F2U a0, a1;  a0.u = acc0;  a1.u = acc1;
        g_s[j] = (a0.f.x + a0.f.y) + (a1.f.x + a1.f.y);
        __syncthreads();
        if (j < HH) {
            float r = sigmoid_fast(gir + g_s[j]);
            float z = sigmoid_fast(giz + g_s[HH + j]);
            float n = tanh_fast(gin + r * g_s[2 * HH + j]);
            float hn = (1.f - z) * n + z * h_s[j];
            h_s[j] = hn;
            pmax = fmaxf(pmax, hn);
        }
        __syncthreads();
    }
    if (j < HH) d_pooled[b * (2 * HH) + dir * HH + j] = pmax;
}

__global__ void __launch_bounds__(128) out_kernel(
    const float* __restrict__ Wout, const float* __restrict__ bout,
    float* __restrict__ out)
{
    const int b = blockIdx.x;
    const int tid = threadIdx.x;
    __shared__ float p_s[2 * HH];
    p_s[tid]      = d_pooled[b * 2 * HH + tid];
    p_s[tid + HH] = d_pooled[b * 2 * HH + HH + tid];
    __syncthreads();
    if (tid < LBL) {
        const float* wr = Wout + (size_t)tid * 2 * HH;
        float acc = bout[tid];
#pragma unroll 8
        for (int k = 0; k < 2 * HH; k++) acc = fmaf(wr[k], p_s[k], acc);
        out[b * LBL + tid] = acc;
    }
}

// ---------------- launch ---------------------------------------------------
extern "C" void kernel_launch(void* const* d_in, const int* in_sizes, int n_in,
                              void* d_out, int out_size) {
    const int*   tokens = (const int*)  d_in[0];
    const float* emb    = (const float*)d_in[1];
    const float* Wc_w   = (const float*)d_in[2];
    const float* Wc_b   = (const float*)d_in[3];
    const float* Wih_f  = (const float*)d_in[4];
    const float* Whh_f  = (const float*)d_in[5];
    const float* bih_f  = (const float*)d_in[6];
    const float* bhh_f  = (const float*)d_in[7];
    const float* Wih_b  = (const float*)d_in[8];
    const float* Whh_b  = (const float*)d_in[9];
    const float* bih_b  = (const float*)d_in[10];
    const float* bhh_b  = (const float*)d_in[11];
    const float* Wout   = (const float*)d_in[12];
    const float* bout   = (const float*)d_in[13];
    float* out = (float*)d_out;

    (void)in_sizes; (void)n_in; (void)out_size;

    cudaFuncSetAttribute(gemm3_mma_kernel,
                         cudaFuncAttributeMaxDynamicSharedMemorySize,
                         GEMM_SMEM_BYTES);

    float* dP = nullptr;  cudaGetSymbolAddress((void**)&dP, d_P);
    float* dG = nullptr;  cudaGetSymbolAddress((void**)&dG, d_gi);
    float* dE = nullptr;  cudaGetSymbolAddress((void**)&dE, d_enc);

    transpose_whh_kernel<<<(2 * G3 * HH + 255) / 256, 256>>>(Whh_f, Whh_b);

    // P = emb @ Wc_w^T  (tensor-core, 3-term bf16 split), tiles 128x64
    gemm3_mma_kernel<<<dim3((VV + 127) / 128, 2), 256, GEMM_SMEM_BYTES>>>(
        emb, VV, Wc_w, nullptr, nullptr, nullptr, dP, 128);

    encode_kernel<<<BL, 128>>>(tokens, Wc_b);

    // gi = enc @ [Wih_f;Wih_b]^T + bias  (tensor-core), tiles 128x64
    gemm3_mma_kernel<<<dim3(BL / 128, G6 / 64), 256, GEMM_SMEM_BYTES>>>(
        dE, BL, Wih_f, Wih_b, bih_f, bih_b, dG, G6);

    gru_kernel<<<128, 384>>>(bhh_f, bhh_b);
    out_kernel<<<BB, 128>>>(Wout, bout, out);
}